// round 2
// baseline (speedup 1.0000x reference)
#include <cuda_runtime.h>

#define N 512
#define D 512

// Scratch (no allocation allowed in kernel_launch)
__device__ float g_u[N * D];   // u[i][h] = sum_d he[i,d] * W0_w[h, d]
__device__ float g_v[N * D];   // v[j][h] = sum_d he[j,d] * W0_w[h, D+d] + b[h]
__device__ float g_a[N * N];   // softmax(p) rows

// ---------------------------------------------------------------------------
// Kernel A: u and v via two NT-GEMMs (blockIdx.z selects which half of W0_w).
// 64x64 tile, TK=16, 256 threads, 4x4 outputs/thread.
// ---------------------------------------------------------------------------
#define ATI 64
#define ATK 16
#define APAD 4   // stride 68 floats = 272B, 16B-aligned, conflict-free LDS.128

__global__ __launch_bounds__(256) void gemm_uv_kernel(
    const float* __restrict__ he, const float* __restrict__ W,
    const float* __restrict__ b)
{
    __shared__ float as[ATK][ATI + APAD];   // [k][i]
    __shared__ float bs[ATK][ATI + APAD];   // [k][h]

    const int which = blockIdx.z;           // 0 -> u, 1 -> v
    const int h0 = blockIdx.x * ATI;
    const int i0 = blockIdx.y * ATI;
    const int koff = which ? D : 0;
    const int tid = threadIdx.x;
    const int tx = tid & 15;                // h sub-tile
    const int ty = tid >> 4;                // i sub-tile

    const int lr = tid >> 2;                // 0..63 (row for cooperative loads)
    const int lk = (tid & 3) << 2;          // 0,4,8,12

    float acc[4][4] = {};

    for (int k0 = 0; k0 < D; k0 += ATK) {
        float4 va = *(const float4*)(he + (size_t)(i0 + lr) * D + k0 + lk);
        float4 vb = *(const float4*)(W + (size_t)(h0 + lr) * (2 * D) + koff + k0 + lk);
        as[lk + 0][lr] = va.x; as[lk + 1][lr] = va.y;
        as[lk + 2][lr] = va.z; as[lk + 3][lr] = va.w;
        bs[lk + 0][lr] = vb.x; bs[lk + 1][lr] = vb.y;
        bs[lk + 2][lr] = vb.z; bs[lk + 3][lr] = vb.w;
        __syncthreads();

        #pragma unroll
        for (int kk = 0; kk < ATK; kk++) {
            float4 a4 = *(const float4*)&as[kk][ty * 4];
            float4 b4 = *(const float4*)&bs[kk][tx * 4];
            float ar[4] = {a4.x, a4.y, a4.z, a4.w};
            float br[4] = {b4.x, b4.y, b4.z, b4.w};
            #pragma unroll
            for (int r = 0; r < 4; r++)
                #pragma unroll
                for (int c = 0; c < 4; c++)
                    acc[r][c] = fmaf(ar[r], br[c], acc[r][c]);
        }
        __syncthreads();
    }

    float* out = which ? g_v : g_u;
    #pragma unroll
    for (int r = 0; r < 4; r++) {
        const int row = i0 + ty * 4 + r;
        #pragma unroll
        for (int c = 0; c < 4; c++) {
            const int col = h0 + tx * 4 + c;
            float val = acc[r][c];
            if (which) val += b[col];       // fold W0_b into v
            out[(size_t)row * D + col] = val;
        }
    }
}

// ---------------------------------------------------------------------------
// Kernel B: pairwise p[i,j] = sum_h relu(u[i,h]+v[j,h])*w1[h], then softmax,
// writes normalized attention rows to g_a.
// CTA = 4 i-rows. 256 threads: thread owns (2 i-rows, 1 j) -> v reused 2x in
// registers. j-tile = 128, h split into 2 chunks of 256 to fit v_s in SMEM.
// W1_b dropped: softmax is shift-invariant.
// ---------------------------------------------------------------------------
#define BI 4
#define BJ 128
#define HCH 256
#define VSTR (HCH + 4)   // 260 floats = 1040B = 65*16, aligned + conflict-free

__global__ __launch_bounds__(256) void pairwise_kernel(
    const float* __restrict__ w1)
{
    extern __shared__ float smem[];
    float* v_s   = smem;                        // [BJ][VSTR]      33280 fl
    float* u_s   = v_s + BJ * VSTR;             // [BI][D]          2048 fl
    float* w_s   = u_s + BI * D;                // [D]               512 fl
    float* p_s   = w_s + D;                     // [BI][N]          2048 fl
    float* inv_s = p_s + BI * N;                // [BI]

    const int tid = threadIdx.x;
    const int i0 = blockIdx.x * BI;
    const int ipair = tid >> 7;                 // 0..1 -> rows {2*ipair, 2*ipair+1}
    const int tj = tid & 127;                   // 0..127

    // stage u rows + w1
    {
        const float4* src = (const float4*)(g_u + (size_t)i0 * D);
        float4* dst = (float4*)u_s;
        for (int m = tid; m < BI * D / 4; m += 256) dst[m] = src[m];
        if (tid < D / 4) ((float4*)w_s)[tid] = ((const float4*)w1)[tid];
    }

    const float* vrow = v_s + tj * VSTR;

    for (int j0 = 0; j0 < N; j0 += BJ) {
        float acc0a = 0.f, acc0b = 0.f, acc1a = 0.f, acc1b = 0.f;
        for (int cc = 0; cc < D; cc += HCH) {
            __syncthreads();   // previous v_s consumers done (also covers u_s staging)
            // load v tile: BJ rows x HCH cols
            for (int m = tid; m < BJ * HCH / 4; m += 256) {
                const int r = m >> 6;          // HCH/4 = 64 float4 per row
                const int c4 = (m & 63) << 2;
                *(float4*)&v_s[r * VSTR + c4] =
                    *(const float4*)&g_v[(size_t)(j0 + r) * D + cc + c4];
            }
            __syncthreads();

            const float* u0p = u_s + (2 * ipair) * D + cc;
            const float* u1p = u0p + D;
            const float* wp = w_s + cc;
            #pragma unroll 4
            for (int h = 0; h < HCH; h += 4) {
                float4 vv = *(const float4*)&vrow[h];
                float4 ua = *(const float4*)&u0p[h];
                float4 ub = *(const float4*)&u1p[h];
                float4 ww = *(const float4*)&wp[h];
                acc0a = fmaf(fmaxf(ua.x + vv.x, 0.f), ww.x, acc0a);
                acc0b = fmaf(fmaxf(ua.y + vv.y, 0.f), ww.y, acc0b);
                acc0a = fmaf(fmaxf(ua.z + vv.z, 0.f), ww.z, acc0a);
                acc0b = fmaf(fmaxf(ua.w + vv.w, 0.f), ww.w, acc0b);
                acc1a = fmaf(fmaxf(ub.x + vv.x, 0.f), ww.x, acc1a);
                acc1b = fmaf(fmaxf(ub.y + vv.y, 0.f), ww.y, acc1b);
                acc1a = fmaf(fmaxf(ub.z + vv.z, 0.f), ww.z, acc1a);
                acc1b = fmaf(fmaxf(ub.w + vv.w, 0.f), ww.w, acc1b);
            }
        }
        p_s[(2 * ipair + 0) * N + j0 + tj] = acc0a + acc0b;
        p_s[(2 * ipair + 1) * N + j0 + tj] = acc1a + acc1b;
    }
    __syncthreads();

    // softmax per row: warp w (<BI) handles row w
    const int warp = tid >> 5, lane = tid & 31;
    if (warp < BI) {
        float* prow = p_s + warp * N;
        float m = -1e30f;
        for (int j = lane; j < N; j += 32) m = fmaxf(m, prow[j]);
        #pragma unroll
        for (int o = 16; o; o >>= 1) m = fmaxf(m, __shfl_xor_sync(0xffffffffu, m, o));
        float s = 0.f;
        for (int j = lane; j < N; j += 32) {
            float e = __expf(prow[j] - m);
            prow[j] = e;
            s += e;
        }
        #pragma unroll
        for (int o = 16; o; o >>= 1) s += __shfl_xor_sync(0xffffffffu, s, o);
        if (lane == 0) inv_s[warp] = 1.f / s;
    }
    __syncthreads();

    // write normalized attention rows
    for (int m = tid; m < BI * N / 4; m += 256) {
        const int i = m >> 7;                 // N/4 = 128 float4 per row
        const int jj = m & 127;
        float4 e = ((const float4*)(p_s + i * N))[jj];
        const float s = inv_s[i];
        e.x *= s; e.y *= s; e.z *= s; e.w *= s;
        ((float4*)(g_a + (size_t)(i0 + i) * N))[jj] = e;
    }
}

// ---------------------------------------------------------------------------
// Kernel C: out = a @ he  (NN GEMM, 32x64 tile, TK=32, 256 threads, 2x4/thread)
// ---------------------------------------------------------------------------
#define CTI 32
#define CTC 64
#define CTK 32

__global__ __launch_bounds__(256) void out_gemm_kernel(
    const float* __restrict__ he, float* __restrict__ out)
{
    __shared__ float as[CTK][CTI + 2];   // stride 34 (8B aligned for float2)
    __shared__ float bs[CTK][CTC + 4];   // stride 68 (16B aligned)

    const int c0 = blockIdx.x * CTC;
    const int i0 = blockIdx.y * CTI;
    const int tid = threadIdx.x;
    const int tx = tid & 15;             // 4 cols each
    const int ty = tid >> 4;             // 2 rows each

    float acc[2][4] = {};

    for (int k0 = 0; k0 < N; k0 += CTK) {
        // a tile transpose load: 32 i x 32 k
        {
            const int r = tid >> 3;              // 0..31 (i)
            const int kk = (tid & 7) << 2;       // 0..28 (k)
            float4 va = *(const float4*)&g_a[(size_t)(i0 + r) * N + k0 + kk];
            as[kk + 0][r] = va.x; as[kk + 1][r] = va.y;
            as[kk + 2][r] = va.z; as[kk + 3][r] = va.w;
        }
        // he tile: 32 k x 64 c
        for (int m = tid; m < CTK * CTC / 4; m += 256) {
            const int r = m >> 4;
            const int c4 = (m & 15) << 2;
            *(float4*)&bs[r][c4] = *(const float4*)&he[(size_t)(k0 + r) * D + c0 + c4];
        }
        __syncthreads();

        #pragma unroll
        for (int kk = 0; kk < CTK; kk++) {
            float2 a2 = *(const float2*)&as[kk][ty * 2];
            float4 b4 = *(const float4*)&bs[kk][tx * 4];
            acc[0][0] = fmaf(a2.x, b4.x, acc[0][0]);
            acc[0][1] = fmaf(a2.x, b4.y, acc[0][1]);
            acc[0][2] = fmaf(a2.x, b4.z, acc[0][2]);
            acc[0][3] = fmaf(a2.x, b4.w, acc[0][3]);
            acc[1][0] = fmaf(a2.y, b4.x, acc[1][0]);
            acc[1][1] = fmaf(a2.y, b4.y, acc[1][1]);
            acc[1][2] = fmaf(a2.y, b4.z, acc[1][2]);
            acc[1][3] = fmaf(a2.y, b4.w, acc[1][3]);
        }
        __syncthreads();
    }

    #pragma unroll
    for (int r = 0; r < 2; r++) {
        float4 o = make_float4(acc[r][0], acc[r][1], acc[r][2], acc[r][3]);
        *(float4*)&out[(size_t)(i0 + ty * 2 + r) * D + c0 + tx * 4] = o;
    }
}

// ---------------------------------------------------------------------------
extern "C" void kernel_launch(void* const* d_in, const int* in_sizes, int n_in,
                              void* d_out, int out_size)
{
    const float* he  = (const float*)d_in[0];   // (512, 512)
    const float* W0w = (const float*)d_in[1];   // (512, 1024)
    const float* W0b = (const float*)d_in[2];   // (512,)
    const float* W1w = (const float*)d_in[3];   // (1, 512)
    // d_in[4] = W1_b: softmax shift-invariant -> unused
    float* out = (float*)d_out;

    const size_t smemB =
        (size_t)(BJ * VSTR + BI * D + D + BI * N + 8) * sizeof(float);
    cudaFuncSetAttribute(pairwise_kernel,
                         cudaFuncAttributeMaxDynamicSharedMemorySize, (int)smemB);

    dim3 gA(D / ATI, N / ATI, 2);
    gemm_uv_kernel<<<gA, 256>>>(he, W0w, W0b);

    pairwise_kernel<<<N / BI, 256, smemB>>>(W1w);

    dim3 gC(D / CTC, N / CTI);
    out_gemm_kernel<<<gC, 256>>>(he, out);
}

// round 4
// speedup vs baseline: 1.6616x; 1.6616x over previous
#include <cuda_runtime.h>

#define N 512
#define D 512

__device__ float g_u[N * D];   // u[i][h]
__device__ float g_v[N * D];   // v[j][h] (+W0_b folded)
__device__ float g_a[N * N];   // softmax rows

typedef unsigned long long u64;

// ---- packed f32x2 helpers (sm_100+) --------------------------------------
__device__ __forceinline__ void fma2(u64& d, u64 a, u64 b) {
    asm("fma.rn.f32x2 %0, %1, %2, %3;" : "=l"(d) : "l"(a), "l"(b), "l"(d));
}
__device__ __forceinline__ u64 add2(u64 a, u64 b) {
    u64 d; asm("add.rn.f32x2 %0, %1, %2;" : "=l"(d) : "l"(a), "l"(b)); return d;
}
__device__ __forceinline__ u64 pk(float x, float y) {
    u64 d; asm("mov.b64 %0, {%1, %2};" : "=l"(d) : "f"(x), "f"(y)); return d;
}
__device__ __forceinline__ float2 upk(u64 v) {
    float2 d; asm("mov.b64 {%0, %1}, %2;" : "=f"(d.x), "=f"(d.y) : "l"(v)); return d;
}
__device__ __forceinline__ void cpa16(float* dst, const float* src) {
    unsigned sa = (unsigned)__cvta_generic_to_shared(dst);
    asm volatile("cp.async.cg.shared.global [%0], [%1], 16;" :: "r"(sa), "l"(src));
}

// ---------------------------------------------------------------------------
// Kernel A: u,v NT-GEMMs. 64x64 tile, smem [row][k] (stride 36), pack-k FFMA2.
// Thread tile 4x4 with strided rows/cols (ty+16r, tx+16c) -> conflict-free LDS.
// ---------------------------------------------------------------------------
#define AK 32
#define AST 36

__global__ __launch_bounds__(256) void gemm_uv_kernel(
    const float* __restrict__ he, const float* __restrict__ W,
    const float* __restrict__ b)
{
    __shared__ float as[64 * AST];   // [i][k]
    __shared__ float bs[64 * AST];   // [h][k]

    const int which = blockIdx.z;
    const int h0 = blockIdx.x * 64;
    const int i0 = blockIdx.y * 64;
    const int koff = which ? D : 0;
    const int tid = threadIdx.x;
    const int tx = tid & 15;
    const int ty = tid >> 4;

    u64 acc[4][4] = {};

    for (int k0 = 0; k0 < D; k0 += AK) {
        #pragma unroll
        for (int m = tid; m < 512; m += 256) {      // 64 rows x 8 float4
            const int r = m >> 3, kq = (m & 7) << 2;
            *(float4*)&as[r * AST + kq] =
                *(const float4*)&he[(size_t)(i0 + r) * D + k0 + kq];
            *(float4*)&bs[r * AST + kq] =
                *(const float4*)&W[(size_t)(h0 + r) * (2 * D) + koff + k0 + kq];
        }
        __syncthreads();

        #pragma unroll
        for (int kk = 0; kk < AK; kk += 4) {
            ulonglong2 av[4], bv[4];
            #pragma unroll
            for (int r = 0; r < 4; r++)
                av[r] = *(const ulonglong2*)&as[(ty + 16 * r) * AST + kk];
            #pragma unroll
            for (int c = 0; c < 4; c++)
                bv[c] = *(const ulonglong2*)&bs[(tx + 16 * c) * AST + kk];
            #pragma unroll
            for (int r = 0; r < 4; r++)
                #pragma unroll
                for (int c = 0; c < 4; c++) {
                    fma2(acc[r][c], av[r].x, bv[c].x);
                    fma2(acc[r][c], av[r].y, bv[c].y);
                }
        }
        __syncthreads();
    }

    float* out = which ? g_v : g_u;
    #pragma unroll
    for (int r = 0; r < 4; r++) {
        const int row = i0 + ty + 16 * r;
        #pragma unroll
        for (int c = 0; c < 4; c++) {
            const int col = h0 + tx + 16 * c;
            float2 f = upk(acc[r][c]);
            float val = f.x + f.y;
            if (which) val += __ldg(&b[col]);
            out[(size_t)row * D + col] = val;
        }
    }
}

// ---------------------------------------------------------------------------
// Kernel B: pairwise + softmax. CTA = 4 i-rows x all 512 j.
// Thread: 4 i-rows x 2 j (j = tid, tid+256). h chunked (32), cp.async
// double-buffered v tiles. u/w1 are warp-uniform broadcasts from smem.
// ---------------------------------------------------------------------------
#define HCH 32
#define VST 36
#define NCH (D / HCH)

__global__ __launch_bounds__(256) void pairwise_kernel(
    const float* __restrict__ w1)
{
    extern __shared__ float sm[];
    float* v_s   = sm;                         // [2][512][VST]
    float* u_s   = sm + 2 * 512 * VST;         // [4][512]
    float* w_s   = u_s + 4 * 512;              // [512]
    float* p_s   = w_s + 512;                  // [4][512]
    float* inv_s = p_s + 4 * 512;              // [4]

    const int tid = threadIdx.x;
    const int i0 = blockIdx.x * 4;

    // stage u rows + w1
    for (int m = tid; m < 4 * 512 / 4; m += 256)
        ((float4*)u_s)[m] = ((const float4*)(g_u + (size_t)i0 * D))[m];
    if (tid < 128) ((float4*)w_s)[tid] = ((const float4*)w1)[tid];

    // prologue: chunk 0
    {
        const float* src = g_v;
        for (int m = tid; m < 512 * (HCH / 4); m += 256) {
            const int j = m >> 3, kq = (m & 7) << 2;
            cpa16(v_s + j * VST + kq, src + (size_t)j * D + kq);
        }
        asm volatile("cp.async.commit_group;");
    }

    u64 acc[4][2] = {};
    const int j1 = tid, j2 = tid + 256;

    for (int ch = 0; ch < NCH; ch++) {
        if (ch + 1 < NCH) {
            float* buf = v_s + ((ch + 1) & 1) * 512 * VST;
            const float* src = g_v + (ch + 1) * HCH;
            for (int m = tid; m < 512 * (HCH / 4); m += 256) {
                const int j = m >> 3, kq = (m & 7) << 2;
                cpa16(buf + j * VST + kq, src + (size_t)j * D + kq);
            }
            asm volatile("cp.async.commit_group;");
            asm volatile("cp.async.wait_group 1;");
        } else {
            asm volatile("cp.async.wait_group 0;");
        }
        __syncthreads();

        const float* vb = v_s + (ch & 1) * 512 * VST;
        const int cc = ch * HCH;
        #pragma unroll
        for (int kk = 0; kk < HCH; kk += 4) {
            ulonglong2 w2 = *(const ulonglong2*)&w_s[cc + kk];
            ulonglong2 va = *(const ulonglong2*)&vb[j1 * VST + kk];
            ulonglong2 vc = *(const ulonglong2*)&vb[j2 * VST + kk];
            #pragma unroll
            for (int i = 0; i < 4; i++) {
                ulonglong2 u2 = *(const ulonglong2*)&u_s[i * 512 + cc + kk];
                u64 t; float2 f;
                t = add2(u2.x, va.x); f = upk(t);
                fma2(acc[i][0], pk(fmaxf(f.x, 0.f), fmaxf(f.y, 0.f)), w2.x);
                t = add2(u2.y, va.y); f = upk(t);
                fma2(acc[i][0], pk(fmaxf(f.x, 0.f), fmaxf(f.y, 0.f)), w2.y);
                t = add2(u2.x, vc.x); f = upk(t);
                fma2(acc[i][1], pk(fmaxf(f.x, 0.f), fmaxf(f.y, 0.f)), w2.x);
                t = add2(u2.y, vc.y); f = upk(t);
                fma2(acc[i][1], pk(fmaxf(f.x, 0.f), fmaxf(f.y, 0.f)), w2.y);
            }
        }
        __syncthreads();
    }

    #pragma unroll
    for (int i = 0; i < 4; i++) {
        float2 f = upk(acc[i][0]);
        p_s[i * 512 + j1] = f.x + f.y;
        f = upk(acc[i][1]);
        p_s[i * 512 + j2] = f.x + f.y;
    }
    __syncthreads();

    // softmax: warp w handles row w
    const int warp = tid >> 5, lane = tid & 31;
    if (warp < 4) {
        float* prow = p_s + warp * 512;
        float m = -1e30f;
        for (int j = lane; j < N; j += 32) m = fmaxf(m, prow[j]);
        #pragma unroll
        for (int o = 16; o; o >>= 1) m = fmaxf(m, __shfl_xor_sync(0xffffffffu, m, o));
        float s = 0.f;
        for (int j = lane; j < N; j += 32) {
            float e = __expf(prow[j] - m);
            prow[j] = e;
            s += e;
        }
        #pragma unroll
        for (int o = 16; o; o >>= 1) s += __shfl_xor_sync(0xffffffffu, s, o);
        if (lane == 0) inv_s[warp] = 1.f / s;
    }
    __syncthreads();

    for (int m = tid; m < 4 * 512 / 4; m += 256) {
        const int i = m >> 7, jj = m & 127;
        float4 e = ((const float4*)(p_s + i * 512))[jj];
        const float s = inv_s[i];
        e.x *= s; e.y *= s; e.z *= s; e.w *= s;
        ((float4*)(g_a + (size_t)(i0 + i) * N))[jj] = e;
    }
}

// ---------------------------------------------------------------------------
// Kernel C: out = a @ he. 32x64 tile, 128 threads, pack-k FFMA2, 4x4/thread.
// he tile transposed into smem [c][k] so k-pairs pack naturally.
// ---------------------------------------------------------------------------
#define CK 32
#define CST 36

__global__ __launch_bounds__(128) void out_gemm_kernel(
    const float* __restrict__ he, float* __restrict__ out)
{
    __shared__ float as[32 * CST];   // [i][k]
    __shared__ float bs[64 * CST];   // [c][k]

    const int c0 = blockIdx.x * 64;
    const int i0 = blockIdx.y * 32;
    const int tid = threadIdx.x;
    const int tx = tid & 15;
    const int ty = tid >> 4;         // 0..7

    u64 acc[4][4] = {};

    for (int k0 = 0; k0 < N; k0 += CK) {
        #pragma unroll
        for (int m = tid; m < 256; m += 128) {       // a: 32 rows x 8 f4
            const int r = m >> 3, kq = (m & 7) << 2;
            *(float4*)&as[r * CST + kq] =
                *(const float4*)&g_a[(size_t)(i0 + r) * N + k0 + kq];
        }
        #pragma unroll
        for (int m = tid; m < 512; m += 128) {       // he: 32k x 64c, transpose
            const int k = m >> 4, cq = (m & 15) << 2;
            float4 v = *(const float4*)&he[(size_t)(k0 + k) * D + c0 + cq];
            bs[(cq + 0) * CST + k] = v.x;
            bs[(cq + 1) * CST + k] = v.y;
            bs[(cq + 2) * CST + k] = v.z;
            bs[(cq + 3) * CST + k] = v.w;
        }
        __syncthreads();

        #pragma unroll
        for (int kk = 0; kk < CK; kk += 4) {
            ulonglong2 av[4], bv[4];
            #pragma unroll
            for (int r = 0; r < 4; r++)
                av[r] = *(const ulonglong2*)&as[(ty + 8 * r) * CST + kk];
            #pragma unroll
            for (int c = 0; c < 4; c++)
                bv[c] = *(const ulonglong2*)&bs[(tx + 16 * c) * CST + kk];
            #pragma unroll
            for (int r = 0; r < 4; r++)
                #pragma unroll
                for (int c = 0; c < 4; c++) {
                    fma2(acc[r][c], av[r].x, bv[c].x);
                    fma2(acc[r][c], av[r].y, bv[c].y);
                }
        }
        __syncthreads();
    }

    #pragma unroll
    for (int r = 0; r < 4; r++) {
        const int row = i0 + ty + 8 * r;
        #pragma unroll
        for (int c = 0; c < 4; c++) {
            float2 f = upk(acc[r][c]);
            out[(size_t)row * D + c0 + tx + 16 * c] = f.x + f.y;
        }
    }
}

// ---------------------------------------------------------------------------
extern "C" void kernel_launch(void* const* d_in, const int* in_sizes, int n_in,
                              void* d_out, int out_size)
{
    const float* he  = (const float*)d_in[0];   // (512, 512)
    const float* W0w = (const float*)d_in[1];   // (512, 1024)
    const float* W0b = (const float*)d_in[2];   // (512,)
    const float* W1w = (const float*)d_in[3];   // (1, 512)
    // d_in[4] = W1_b: softmax shift-invariant -> unused
    float* out = (float*)d_out;

    const size_t smemB =
        (size_t)(2 * 512 * VST + 4 * 512 + 512 + 4 * 512 + 8) * sizeof(float);
    cudaFuncSetAttribute(pairwise_kernel,
                         cudaFuncAttributeMaxDynamicSharedMemorySize, (int)smemB);

    dim3 gA(D / 64, N / 64, 2);                 // 128 CTAs
    gemm_uv_kernel<<<gA, 256>>>(he, W0w, W0b);

    pairwise_kernel<<<N / 4, 256, smemB>>>(W1w); // 128 CTAs

    dim3 gC(D / 64, N / 32);                     // 128 CTAs
    out_gemm_kernel<<<gC, 128>>>(he, out);
}